// round 14
// baseline (speedup 1.0000x reference)
#include <cuda_runtime.h>
#include <math.h>

#define NN   100000
#define EE   1600000
#define INC  64
#define HIDD 128
#define LN_EPS 1e-5f
#define T0   16
#define T1   16
#define BGT  512                          // build kernel block size

typedef unsigned long long ull;

// ---------------- scratch (static device globals; no allocation) ----------------
__device__ int      g_deg[NN];
__device__ int      g_cur[NN];
__device__ int      g_rowTmp[NN];
__device__ int      g_row[NN];
__device__ int      g_bsum[2048];
__device__ int      g_csr[EE];
__device__ float    g_h0[NN * HIDD];
__device__ int      g_is64;
__device__ unsigned g_barrier[8];         // monotonic counters; replay-safe

// ---------------- packed f32x2 helpers ----------------
__device__ __forceinline__ ull pk2(float lo, float hi) {
    ull r; asm("mov.b64 %0,{%1,%2};" : "=l"(r) : "f"(lo), "f"(hi)); return r;
}
__device__ __forceinline__ ull fma2(ull a, ull b, ull c) {
    ull d; asm("fma.rn.f32x2 %0,%1,%2,%3;" : "=l"(d) : "l"(a), "l"(b), "l"(c)); return d;
}
__device__ __forceinline__ float red2(ull v) {
    float lo, hi; asm("mov.b64 {%0,%1},%2;" : "=f"(lo), "=f"(hi) : "l"(v)); return lo + hi;
}

// ---------------- replay-safe grid barrier (all blocks wave-1 resident) ----------------
__device__ __forceinline__ void gsync(int k) {
    __syncthreads();
    if (threadIdx.x == 0) {
        __threadfence();
        unsigned nb = gridDim.x;
        unsigned old = atomicAdd(&g_barrier[k], 1u);
        unsigned target = (old / nb + 1u) * nb;     // this replay's goal
        while (atomicAdd(&g_barrier[k], 0u) < target) __nanosleep(64);
    }
    __syncthreads();
}

// ---------------- single-launch CSR build: detect+zero -> count -> scan -> fill ----------------
__global__ void __launch_bounds__(BGT) k_build(const int* __restrict__ eidx) {
    int tid = threadIdx.x;
    int gtid = blockIdx.x * BGT + tid;
    int gs = gridDim.x * BGT;

    // detect dtype (int64 edge_index has zero high words) + zero degrees
    if (gtid == 0) {
        int all0 = 1;
        #pragma unroll 1
        for (int i = 0; i < 64; i++)
            if (eidx[2 * i + 1] != 0) all0 = 0;
        g_is64 = all0;
    }
    for (int i = gtid; i < NN; i += gs) g_deg[i] = 0;
    gsync(0);

    int is64 = g_is64;

    // count
    if (is64) {
        const long long* p = (const long long*)eidx;
        for (int e = gtid; e < EE; e += gs) { int d = (int)p[EE + e]; atomicAdd(&g_deg[d], 1); }
    } else {
        const int* p = (const int*)eidx;
        for (int e = gtid; e < EE; e += gs) { int d = p[EE + e]; atomicAdd(&g_deg[d], 1); }
    }
    gsync(1);

    // per-block chunked exclusive scan (use __ldcg: atomics updated L2, own L1 may hold stale zeros)
    int chunk = (NN + gridDim.x - 1) / gridDim.x;
    int start = blockIdx.x * chunk;
    __shared__ int ssc[BGT];
    int carry = 0;
    for (int t0 = 0; t0 < chunk; t0 += BGT) {
        int li = t0 + tid;
        int idx = start + li;
        int v = (li < chunk && idx < NN) ? __ldcg(&g_deg[idx]) : 0;
        ssc[tid] = v;
        __syncthreads();
        for (int off = 1; off < BGT; off <<= 1) {
            int tv = (tid >= off) ? ssc[tid - off] : 0;
            __syncthreads();
            ssc[tid] += tv;
            __syncthreads();
        }
        if (li < chunk && idx < NN) g_rowTmp[idx] = ssc[tid] - v + carry;
        carry += ssc[BGT - 1];
        __syncthreads();
    }
    if (tid == 0) g_bsum[blockIdx.x] = carry;
    gsync(2);

    // exclusive block offset (each block redundantly sums predecessors) + apply
    __shared__ int sboff;
    if (tid < 32) {
        int acc = 0;
        for (int i = tid; i < blockIdx.x; i += 32) acc += __ldcg(&g_bsum[i]);
        #pragma unroll
        for (int o = 16; o > 0; o >>= 1) acc += __shfl_xor_sync(0xFFFFFFFFu, acc, o);
        if (tid == 0) sboff = acc;
    }
    __syncthreads();
    int boff = sboff;
    for (int li = tid; li < chunk; li += BGT) {
        int idx = start + li;
        if (idx < NN) { int r = g_rowTmp[idx] + boff; g_row[idx] = r; g_cur[idx] = r; }
    }
    gsync(3);

    // fill
    if (is64) {
        const long long* p = (const long long*)eidx;
        for (int e = gtid; e < EE; e += gs) {
            int s = (int)p[e], d = (int)p[EE + e];
            int pos = atomicAdd(&g_cur[d], 1);
            g_csr[pos] = s;
        }
    } else {
        const int* p = (const int*)eidx;
        for (int e = gtid; e < EE; e += gs) {
            int s = p[e], d = p[EE + e];
            int pos = atomicAdd(&g_cur[d], 1);
            g_csr[pos] = s;
        }
    }
}

// ---------------- layer-0 fused: gather-max + dots + LN + ReLU (256 thr, 8 warps) ----------------
__global__ void __launch_bounds__(256) k_sage0(const float* __restrict__ x,
                                               const float* __restrict__ Wl,
                                               const float* __restrict__ bl,
                                               const float* __restrict__ Wr,
                                               const float* __restrict__ gam,
                                               const float* __restrict__ bet) {
    int t = threadIdx.x;
    int j = t & 127, h = t >> 7;
    int lane = t & 31, w = t >> 5;
    int base = blockIdx.x * T0;

    ull wl2[16], wr2[16];                 // half-rows: 64 regs of weights
    {
        const float4* pl = (const float4*)(Wl + j * 64 + h * 32);
        const float4* pr = (const float4*)(Wr + j * 64 + h * 32);
        #pragma unroll
        for (int k = 0; k < 8; k++) {
            float4 a = pl[k]; wl2[2*k] = pk2(a.x, a.y); wl2[2*k+1] = pk2(a.z, a.w);
            float4 b = pr[k]; wr2[2*k] = pk2(b.x, b.y); wr2[2*k+1] = pk2(b.z, b.w);
        }
    }
    float blj = (h == 0) ? bl[j] : 0.f;
    float gv[4], bv[4];
    #pragma unroll
    for (int i = 0; i < 4; i++) { gv[i] = gam[lane + 32*i]; bv[i] = bet[lane + 32*i]; }

    __shared__ __align__(16) float sa[T0][64];
    __shared__ __align__(16) float sx[T0][64];
    __shared__ __align__(16) float part[T0][256];
    __shared__ int sidx[8][32];

    // stage own-node x rows (coalesced)
    for (int i = t; i < T0 * 64; i += 256) {
        int n = i >> 6, k = i & 63;
        sx[n][k] = x[(base + n) * 64 + k];
    }

    // fused gather-max: warp w -> nodes 2w, 2w+1
    #pragma unroll
    for (int ii = 0; ii < 2; ii++) {
        int n = w * 2 + ii, node = base + n;
        int row = g_row[node], deg = g_deg[node];
        float2 acc = make_float2(-__builtin_huge_valf(), -__builtin_huge_valf());
        for (int b = 0; b < deg; b += 32) {
            int cnt = min(32, deg - b);
            if (b + lane < deg) sidx[w][lane] = g_csr[row + b + lane];
            __syncwarp();
            #pragma unroll 8
            for (int i2 = 0; i2 < cnt; i2++) {
                int s = sidx[w][i2];
                float2 v = ((const float2*)x)[s * 32 + lane];
                acc.x = fmaxf(acc.x, v.x);
                acc.y = fmaxf(acc.y, v.y);
            }
            __syncwarp();
        }
        if (deg == 0) { acc.x = 0.f; acc.y = 0.f; }   // empty neighborhood -> 0
        ((float2*)sa[n])[lane] = acc;
    }
    __syncthreads();

    // Phase A: half-row dots
    for (int n = 0; n < T0; n++) {
        const ulonglong2* a2 = (const ulonglong2*)(sa[n] + h * 32);
        const ulonglong2* x2 = (const ulonglong2*)(sx[n] + h * 32);
        ull c0 = 0, c1 = 0, c2 = 0, c3 = 0;
        #pragma unroll
        for (int k = 0; k < 8; k++) {
            ulonglong2 pa = a2[k];
            ulonglong2 px = x2[k];
            c0 = fma2(wl2[2*k],   pa.x, c0);
            c1 = fma2(wl2[2*k+1], pa.y, c1);
            c2 = fma2(wr2[2*k],   px.x, c2);
            c3 = fma2(wr2[2*k+1], px.y, c3);
        }
        part[n][t] = blj + ((red2(c0) + red2(c1)) + (red2(c2) + red2(c3)));
    }
    __syncthreads();

    // Phase B: warp w -> nodes 2w, 2w+1: combine halves + LN + ReLU
    #pragma unroll
    for (int i = 0; i < 2; i++) {
        int n = w * 2 + i;
        float v0 = part[n][lane]      + part[n][lane + 128];
        float v1 = part[n][lane + 32] + part[n][lane + 160];
        float v2 = part[n][lane + 64] + part[n][lane + 192];
        float v3 = part[n][lane + 96] + part[n][lane + 224];
        float s1 = (v0 + v1) + (v2 + v3);
        float s2 = (v0*v0 + v1*v1) + (v2*v2 + v3*v3);
        #pragma unroll
        for (int o = 16; o > 0; o >>= 1) {
            s1 += __shfl_xor_sync(0xFFFFFFFFu, s1, o);
            s2 += __shfl_xor_sync(0xFFFFFFFFu, s2, o);
        }
        float mu = s1 * (1.f / 128.f);
        float var = s2 * (1.f / 128.f) - mu * mu;
        float rstd = rsqrtf(var + LN_EPS);
        float* dst = g_h0 + (base + n) * 128 + lane;
        dst[0]  = fmaxf((v0 - mu) * rstd * gv[0] + bv[0], 0.f);
        dst[32] = fmaxf((v1 - mu) * rstd * gv[1] + bv[1], 0.f);
        dst[64] = fmaxf((v2 - mu) * rstd * gv[2] + bv[2], 0.f);
        dst[96] = fmaxf((v3 - mu) * rstd * gv[3] + bv[3], 0.f);
    }
}

// ---------------- layer-1 fused: gather-max + dots + LN + head (512 thr, 16 warps) ----------------
__global__ void __launch_bounds__(512) k_sage1(const float* __restrict__ Wl,
                                               const float* __restrict__ bl,
                                               const float* __restrict__ Wr,
                                               const float* __restrict__ gam,
                                               const float* __restrict__ bet,
                                               const float* __restrict__ W1,
                                               const float* __restrict__ b1,
                                               const float* __restrict__ W2,
                                               const float* __restrict__ b2,
                                               float* __restrict__ out) {
    int t = threadIdx.x;
    int j = t & 127, hq = t >> 7;         // quarter index 0..3
    int m = t & 63,  q = t >> 6;          // head segment 0..7
    int lane = t & 31, w = t >> 5;        // 16 warps
    int base = blockIdx.x * T1;

    ull wl2[16], wr2[16], w1p[8];         // quarter-rows: 64 + 16 regs of weights
    {
        const float4* pl = (const float4*)(Wl + j * 128 + hq * 32);
        const float4* pr = (const float4*)(Wr + j * 128 + hq * 32);
        #pragma unroll
        for (int k = 0; k < 8; k++) {
            float4 a = pl[k]; wl2[2*k] = pk2(a.x, a.y); wl2[2*k+1] = pk2(a.z, a.w);
            float4 b = pr[k]; wr2[2*k] = pk2(b.x, b.y); wr2[2*k+1] = pk2(b.z, b.w);
        }
        const float4* p1 = (const float4*)(W1 + m * 128 + q * 16);
        #pragma unroll
        for (int k = 0; k < 4; k++) {
            float4 a = p1[k]; w1p[2*k] = pk2(a.x, a.y); w1p[2*k+1] = pk2(a.z, a.w);
        }
    }
    float blj = (hq == 0) ? bl[j] : 0.f;
    float gv[4], bv[4];
    #pragma unroll
    for (int i = 0; i < 4; i++) { gv[i] = gam[lane + 32*i]; bv[i] = bet[lane + 32*i]; }
    float b1v0 = b1[lane], b1v1 = b1[lane + 32];
    float w2v0 = W2[lane], w2v1 = W2[lane + 32];
    float b2s = b2[0];

    __shared__ __align__(16) float sa[T1][128];
    __shared__ __align__(16) float sh[T1][128];
    __shared__ __align__(16) float part[T1][512];
    __shared__ __align__(16) float sOut[T1][128];
    __shared__ int sidx[16][32];

    // stage own-node h0 rows (coalesced)
    for (int i = t; i < T1 * 128; i += 512) {
        int n = i >> 7, k = i & 127;
        sh[n][k] = g_h0[(base + n) * 128 + k];
    }

    // fused gather-max: warp w -> node w (h0 >= 0, so init 0 handles empty)
    {
        int node = base + w;
        int row = g_row[node], deg = g_deg[node];
        float4 acc = make_float4(0.f, 0.f, 0.f, 0.f);
        for (int b = 0; b < deg; b += 32) {
            int cnt = min(32, deg - b);
            if (b + lane < deg) sidx[w][lane] = g_csr[row + b + lane];
            __syncwarp();
            #pragma unroll 8
            for (int i2 = 0; i2 < cnt; i2++) {
                int s = sidx[w][i2];
                float4 v = ((const float4*)g_h0)[s * 32 + lane];
                acc.x = fmaxf(acc.x, v.x);
                acc.y = fmaxf(acc.y, v.y);
                acc.z = fmaxf(acc.z, v.z);
                acc.w = fmaxf(acc.w, v.w);
            }
            __syncwarp();
        }
        ((float4*)sa[w])[lane] = acc;
    }
    __syncthreads();

    // Phase A: quarter-row dots
    for (int n = 0; n < T1; n++) {
        const ulonglong2* a2 = (const ulonglong2*)(sa[n] + hq * 32);
        const ulonglong2* h4 = (const ulonglong2*)(sh[n] + hq * 32);
        ull c0 = 0, c1 = 0, c2 = 0, c3 = 0;
        #pragma unroll
        for (int k = 0; k < 8; k++) {
            ulonglong2 pa = a2[k];
            ulonglong2 ph = h4[k];
            c0 = fma2(wl2[2*k],   pa.x, c0);
            c1 = fma2(wl2[2*k+1], pa.y, c1);
            c2 = fma2(wr2[2*k],   ph.x, c2);
            c3 = fma2(wr2[2*k+1], ph.y, c3);
        }
        part[n][t] = blj + ((red2(c0) + red2(c1)) + (red2(c2) + red2(c3)));
    }
    __syncthreads();

    // Phase B: warp w -> node w: combine quarters + LN + ReLU
    {
        int n = w;
        float v0 = part[n][lane]      + part[n][lane + 128] + part[n][lane + 256] + part[n][lane + 384];
        float v1 = part[n][lane + 32] + part[n][lane + 160] + part[n][lane + 288] + part[n][lane + 416];
        float v2 = part[n][lane + 64] + part[n][lane + 192] + part[n][lane + 320] + part[n][lane + 448];
        float v3 = part[n][lane + 96] + part[n][lane + 224] + part[n][lane + 352] + part[n][lane + 480];
        float s1 = (v0 + v1) + (v2 + v3);
        float s2 = (v0*v0 + v1*v1) + (v2*v2 + v3*v3);
        #pragma unroll
        for (int o = 16; o > 0; o >>= 1) {
            s1 += __shfl_xor_sync(0xFFFFFFFFu, s1, o);
            s2 += __shfl_xor_sync(0xFFFFFFFFu, s2, o);
        }
        float mu = s1 * (1.f / 128.f);
        float var = s2 * (1.f / 128.f) - mu * mu;
        float rstd = rsqrtf(var + LN_EPS);
        sOut[n][lane]      = fmaxf((v0 - mu) * rstd * gv[0] + bv[0], 0.f);
        sOut[n][lane + 32] = fmaxf((v1 - mu) * rstd * gv[1] + bv[1], 0.f);
        sOut[n][lane + 64] = fmaxf((v2 - mu) * rstd * gv[2] + bv[2], 0.f);
        sOut[n][lane + 96] = fmaxf((v3 - mu) * rstd * gv[3] + bv[3], 0.f);
    }
    __syncthreads();

    // Phase C1: head segment dots (16 floats = 4 ulonglong2 -> k < 4)
    for (int n = 0; n < T1; n++) {
        const ulonglong2* s2p = (const ulonglong2*)(sOut[n] + q * 16);
        ull c0 = 0, c1 = 0;
        #pragma unroll
        for (int k = 0; k < 4; k++) {
            ulonglong2 pv = s2p[k];
            c0 = fma2(w1p[2*k],   pv.x, c0);
            c1 = fma2(w1p[2*k+1], pv.y, c1);
        }
        part[n][t] = red2(c0) + red2(c1);
    }
    __syncthreads();

    // Phase C2: warp w -> node w: combine segments, relu*W2, reduce, sigmoid
    {
        int n = w;
        float h0 = b1v0, h1 = b1v1;
        #pragma unroll
        for (int qq = 0; qq < 8; qq++) {
            h0 += part[n][qq * 64 + lane];
            h1 += part[n][qq * 64 + 32 + lane];
        }
        float z = fmaxf(h0, 0.f) * w2v0 + fmaxf(h1, 0.f) * w2v1;
        #pragma unroll
        for (int o = 16; o > 0; o >>= 1)
            z += __shfl_xor_sync(0xFFFFFFFFu, z, o);
        if (lane == 0)
            out[base + n] = 1.f / (1.f + expf(-(z + b2s)));
    }
}

// ---------------- launch ----------------
extern "C" void kernel_launch(void* const* d_in, const int* in_sizes, int n_in,
                              void* d_out, int out_size) {
    const float* x   = (const float*)d_in[0];
    const void*  ei  = d_in[1];
    const float* Wl0 = (const float*)d_in[2];
    const float* bl0 = (const float*)d_in[3];
    const float* Wr0 = (const float*)d_in[4];
    const float* g0  = (const float*)d_in[5];
    const float* be0 = (const float*)d_in[6];
    const float* Wl1 = (const float*)d_in[7];
    const float* bl1 = (const float*)d_in[8];
    const float* Wr1 = (const float*)d_in[9];
    const float* g1  = (const float*)d_in[10];
    const float* be1 = (const float*)d_in[11];
    const float* W1  = (const float*)d_in[12];
    const float* b1  = (const float*)d_in[13];
    const float* W2  = (const float*)d_in[14];
    const float* b2  = (const float*)d_in[15];
    float* out = (float*)d_out;

    // residency-guaranteed grid for the barrier kernel (deterministic per device)
    int dev = 0, smCount = 0, occ = 0;
    cudaGetDevice(&dev);
    cudaDeviceGetAttribute(&smCount, cudaDevAttrMultiProcessorCount, dev);
    cudaOccupancyMaxActiveBlocksPerMultiprocessor(&occ, k_build, BGT, 0);
    if (occ < 1) occ = 1;
    int G = smCount * occ;
    if (G > 2048) G = 2048;
    if (G < 1) G = 1;

    k_build<<<G, BGT>>>((const int*)ei);                                        // 1
    k_sage0<<<NN / T0, 256>>>(x, Wl0, bl0, Wr0, g0, be0);                       // 2
    k_sage1<<<NN / T1, 512>>>(Wl1, bl1, Wr1, g1, be1, W1, b1, W2, b2, out);     // 3
}

// round 15
// speedup vs baseline: 2.0140x; 2.0140x over previous
#include <cuda_runtime.h>
#include <math.h>

#define NN   100000
#define EE   1600000
#define INC  64
#define HIDD 128
#define LN_EPS 1e-5f
#define T0   16
#define T1   16
#define NT   10                           // tiles per block (160 nodes/block, 625 blocks)
#define BGT  512                          // build kernel block size

typedef unsigned long long ull;

// ---------------- scratch (static device globals; no allocation) ----------------
__device__ int      g_deg[NN];
__device__ int      g_cur[NN];
__device__ int      g_rowTmp[NN];
__device__ int      g_row[NN];
__device__ int      g_bsum[2048];
__device__ int      g_csr[EE];
__device__ float    g_agg0f[NN * INC];
__device__ float    g_agg1f[NN * HIDD];
__device__ float    g_h0[NN * HIDD];
__device__ int      g_is64;
__device__ unsigned g_barrier[8];         // monotonic counters; replay-safe

// ---------------- packed f32x2 helpers ----------------
__device__ __forceinline__ ull pk2(float lo, float hi) {
    ull r; asm("mov.b64 %0,{%1,%2};" : "=l"(r) : "f"(lo), "f"(hi)); return r;
}
__device__ __forceinline__ ull fma2(ull a, ull b, ull c) {
    ull d; asm("fma.rn.f32x2 %0,%1,%2,%3;" : "=l"(d) : "l"(a), "l"(b), "l"(c)); return d;
}
__device__ __forceinline__ float red2(ull v) {
    float lo, hi; asm("mov.b64 {%0,%1},%2;" : "=f"(lo), "=f"(hi) : "l"(v)); return lo + hi;
}

// ---------------- replay-safe grid barrier (all blocks wave-1 resident) ----------------
__device__ __forceinline__ void gsync(int k) {
    __syncthreads();
    if (threadIdx.x == 0) {
        __threadfence();
        unsigned nb = gridDim.x;
        unsigned old = atomicAdd(&g_barrier[k], 1u);
        unsigned target = (old / nb + 1u) * nb;
        while (atomicAdd(&g_barrier[k], 0u) < target) __nanosleep(64);
    }
    __syncthreads();
}

// ---------------- single-launch CSR build (measured 62.7us) ----------------
__global__ void __launch_bounds__(BGT) k_build(const int* __restrict__ eidx) {
    int tid = threadIdx.x;
    int gtid = blockIdx.x * BGT + tid;
    int gs = gridDim.x * BGT;

    if (gtid == 0) {
        int all0 = 1;
        #pragma unroll 1
        for (int i = 0; i < 64; i++)
            if (eidx[2 * i + 1] != 0) all0 = 0;
        g_is64 = all0;
    }
    for (int i = gtid; i < NN; i += gs) g_deg[i] = 0;
    gsync(0);

    int is64 = g_is64;

    if (is64) {
        const long long* p = (const long long*)eidx;
        for (int e = gtid; e < EE; e += gs) { int d = (int)p[EE + e]; atomicAdd(&g_deg[d], 1); }
    } else {
        const int* p = (const int*)eidx;
        for (int e = gtid; e < EE; e += gs) { int d = p[EE + e]; atomicAdd(&g_deg[d], 1); }
    }
    gsync(1);

    int chunk = (NN + gridDim.x - 1) / gridDim.x;
    int start = blockIdx.x * chunk;
    __shared__ int ssc[BGT];
    int carry = 0;
    for (int t0 = 0; t0 < chunk; t0 += BGT) {
        int li = t0 + tid;
        int idx = start + li;
        int v = (li < chunk && idx < NN) ? __ldcg(&g_deg[idx]) : 0;
        ssc[tid] = v;
        __syncthreads();
        for (int off = 1; off < BGT; off <<= 1) {
            int tv = (tid >= off) ? ssc[tid - off] : 0;
            __syncthreads();
            ssc[tid] += tv;
            __syncthreads();
        }
        if (li < chunk && idx < NN) g_rowTmp[idx] = ssc[tid] - v + carry;
        carry += ssc[BGT - 1];
        __syncthreads();
    }
    if (tid == 0) g_bsum[blockIdx.x] = carry;
    gsync(2);

    __shared__ int sboff;
    if (tid < 32) {
        int acc = 0;
        for (int i = tid; i < blockIdx.x; i += 32) acc += __ldcg(&g_bsum[i]);
        #pragma unroll
        for (int o = 16; o > 0; o >>= 1) acc += __shfl_xor_sync(0xFFFFFFFFu, acc, o);
        if (tid == 0) sboff = acc;
    }
    __syncthreads();
    int boff = sboff;
    for (int li = tid; li < chunk; li += BGT) {
        int idx = start + li;
        if (idx < NN) { int r = g_rowTmp[idx] + boff; g_row[idx] = r; g_cur[idx] = r; }
    }
    gsync(3);

    if (is64) {
        const long long* p = (const long long*)eidx;
        for (int e = gtid; e < EE; e += gs) {
            int s = (int)p[e], d = (int)p[EE + e];
            int pos = atomicAdd(&g_cur[d], 1);
            g_csr[pos] = s;
        }
    } else {
        const int* p = (const int*)eidx;
        for (int e = gtid; e < EE; e += gs) {
            int s = p[e], d = p[EE + e];
            int pos = atomicAdd(&g_cur[d], 1);
            g_csr[pos] = s;
        }
    }
}

// ---------------- gather-max aggregation: warp per node (high occupancy) ----------------
__global__ void __launch_bounds__(256) k_agg0(const float* __restrict__ x) {
    __shared__ int sidx[8][32];
    int wloc = threadIdx.x >> 5;
    int gw = (blockIdx.x * 256 + threadIdx.x) >> 5;
    int lane = threadIdx.x & 31;
    if (gw >= NN) return;
    int row = g_row[gw], deg = g_deg[gw];
    float2 acc = make_float2(-__builtin_huge_valf(), -__builtin_huge_valf());
    for (int b = 0; b < deg; b += 32) {
        int n = min(32, deg - b);
        if (b + lane < deg) sidx[wloc][lane] = g_csr[row + b + lane];
        __syncwarp();
        #pragma unroll 8
        for (int i = 0; i < n; i++) {
            int s = sidx[wloc][i];
            float2 v = ((const float2*)x)[s * 32 + lane];
            acc.x = fmaxf(acc.x, v.x);
            acc.y = fmaxf(acc.y, v.y);
        }
        __syncwarp();
    }
    if (deg == 0) { acc.x = 0.f; acc.y = 0.f; }
    ((float2*)g_agg0f)[gw * 32 + lane] = acc;
}

__global__ void __launch_bounds__(256) k_agg1() {
    __shared__ int sidx[8][32];
    int wloc = threadIdx.x >> 5;
    int gw = (blockIdx.x * 256 + threadIdx.x) >> 5;
    int lane = threadIdx.x & 31;
    if (gw >= NN) return;
    int row = g_row[gw], deg = g_deg[gw];
    float4 acc = make_float4(0.f, 0.f, 0.f, 0.f);   // h0 >= 0; empty -> 0
    for (int b = 0; b < deg; b += 32) {
        int n = min(32, deg - b);
        if (b + lane < deg) sidx[wloc][lane] = g_csr[row + b + lane];
        __syncwarp();
        #pragma unroll 8
        for (int i = 0; i < n; i++) {
            int s = sidx[wloc][i];
            float4 v = ((const float4*)g_h0)[s * 32 + lane];
            acc.x = fmaxf(acc.x, v.x);
            acc.y = fmaxf(acc.y, v.y);
            acc.z = fmaxf(acc.z, v.z);
            acc.w = fmaxf(acc.w, v.w);
        }
        __syncwarp();
    }
    ((float4*)g_agg1f)[gw * 32 + lane] = acc;
}

// ---------------- layer-0: weights loaded once per 160 nodes (10 tiles) ----------------
__global__ void __launch_bounds__(256) k_sage0(const float* __restrict__ x,
                                               const float* __restrict__ Wl,
                                               const float* __restrict__ bl,
                                               const float* __restrict__ Wr,
                                               const float* __restrict__ gam,
                                               const float* __restrict__ bet) {
    int t = threadIdx.x;
    int j = t & 127, h = t >> 7;
    int lane = t & 31, w = t >> 5;

    ull wl2[16], wr2[16];                 // half-rows: 64 regs of weights
    {
        const float4* pl = (const float4*)(Wl + j * 64 + h * 32);
        const float4* pr = (const float4*)(Wr + j * 64 + h * 32);
        #pragma unroll
        for (int k = 0; k < 8; k++) {
            float4 a = pl[k]; wl2[2*k] = pk2(a.x, a.y); wl2[2*k+1] = pk2(a.z, a.w);
            float4 b = pr[k]; wr2[2*k] = pk2(b.x, b.y); wr2[2*k+1] = pk2(b.z, b.w);
        }
    }
    float blj = (h == 0) ? bl[j] : 0.f;
    float gv[4], bv[4];
    #pragma unroll
    for (int i = 0; i < 4; i++) { gv[i] = gam[lane + 32*i]; bv[i] = bet[lane + 32*i]; }

    __shared__ __align__(16) float sa[T0][64];
    __shared__ __align__(16) float sx[T0][64];
    __shared__ __align__(16) float part[T0][256];

    for (int tile = 0; tile < NT; tile++) {
        int base = blockIdx.x * (T0 * NT) + tile * T0;

        for (int i = t; i < T0 * 64; i += 256) {
            int n = i >> 6, k = i & 63;
            sa[n][k] = g_agg0f[(base + n) * 64 + k];
            sx[n][k] = x[(base + n) * 64 + k];
        }
        __syncthreads();

        // Phase A: half-row dots
        for (int n = 0; n < T0; n++) {
            const ulonglong2* a2 = (const ulonglong2*)(sa[n] + h * 32);
            const ulonglong2* x2 = (const ulonglong2*)(sx[n] + h * 32);
            ull c0 = 0, c1 = 0, c2 = 0, c3 = 0;
            #pragma unroll
            for (int k = 0; k < 8; k++) {
                ulonglong2 pa = a2[k];
                ulonglong2 px = x2[k];
                c0 = fma2(wl2[2*k],   pa.x, c0);
                c1 = fma2(wl2[2*k+1], pa.y, c1);
                c2 = fma2(wr2[2*k],   px.x, c2);
                c3 = fma2(wr2[2*k+1], px.y, c3);
            }
            part[n][t] = blj + ((red2(c0) + red2(c1)) + (red2(c2) + red2(c3)));
        }
        __syncthreads();

        // Phase B: warp w -> nodes 2w, 2w+1
        #pragma unroll
        for (int i = 0; i < 2; i++) {
            int n = w * 2 + i;
            float v0 = part[n][lane]      + part[n][lane + 128];
            float v1 = part[n][lane + 32] + part[n][lane + 160];
            float v2 = part[n][lane + 64] + part[n][lane + 192];
            float v3 = part[n][lane + 96] + part[n][lane + 224];
            float s1 = (v0 + v1) + (v2 + v3);
            float s2 = (v0*v0 + v1*v1) + (v2*v2 + v3*v3);
            #pragma unroll
            for (int o = 16; o > 0; o >>= 1) {
                s1 += __shfl_xor_sync(0xFFFFFFFFu, s1, o);
                s2 += __shfl_xor_sync(0xFFFFFFFFu, s2, o);
            }
            float mu = s1 * (1.f / 128.f);
            float var = s2 * (1.f / 128.f) - mu * mu;
            float rstd = rsqrtf(var + LN_EPS);
            float* dst = g_h0 + (base + n) * 128 + lane;
            dst[0]  = fmaxf((v0 - mu) * rstd * gv[0] + bv[0], 0.f);
            dst[32] = fmaxf((v1 - mu) * rstd * gv[1] + bv[1], 0.f);
            dst[64] = fmaxf((v2 - mu) * rstd * gv[2] + bv[2], 0.f);
            dst[96] = fmaxf((v3 - mu) * rstd * gv[3] + bv[3], 0.f);
        }
        __syncthreads();   // part/sa reuse safety across tiles
    }
}

// ---------------- layer-1: weights loaded once per 160 nodes (10 tiles) ----------------
__global__ void __launch_bounds__(512) k_sage1(const float* __restrict__ Wl,
                                               const float* __restrict__ bl,
                                               const float* __restrict__ Wr,
                                               const float* __restrict__ gam,
                                               const float* __restrict__ bet,
                                               const float* __restrict__ W1,
                                               const float* __restrict__ b1,
                                               const float* __restrict__ W2,
                                               const float* __restrict__ b2,
                                               float* __restrict__ out) {
    int t = threadIdx.x;
    int j = t & 127, hq = t >> 7;         // quarter index 0..3
    int m = t & 63,  q = t >> 6;          // head segment 0..7
    int lane = t & 31, w = t >> 5;        // 16 warps

    ull wl2[16], wr2[16], w1p[8];
    {
        const float4* pl = (const float4*)(Wl + j * 128 + hq * 32);
        const float4* pr = (const float4*)(Wr + j * 128 + hq * 32);
        #pragma unroll
        for (int k = 0; k < 8; k++) {
            float4 a = pl[k]; wl2[2*k] = pk2(a.x, a.y); wl2[2*k+1] = pk2(a.z, a.w);
            float4 b = pr[k]; wr2[2*k] = pk2(b.x, b.y); wr2[2*k+1] = pk2(b.z, b.w);
        }
        const float4* p1 = (const float4*)(W1 + m * 128 + q * 16);
        #pragma unroll
        for (int k = 0; k < 4; k++) {
            float4 a = p1[k]; w1p[2*k] = pk2(a.x, a.y); w1p[2*k+1] = pk2(a.z, a.w);
        }
    }
    float blj = (hq == 0) ? bl[j] : 0.f;
    float gv[4], bv[4];
    #pragma unroll
    for (int i = 0; i < 4; i++) { gv[i] = gam[lane + 32*i]; bv[i] = bet[lane + 32*i]; }
    float b1v0 = b1[lane], b1v1 = b1[lane + 32];
    float w2v0 = W2[lane], w2v1 = W2[lane + 32];
    float b2s = b2[0];

    __shared__ __align__(16) float sa[T1][128];
    __shared__ __align__(16) float sh[T1][128];
    __shared__ __align__(16) float part[T1][512];
    __shared__ __align__(16) float sOut[T1][128];

    for (int tile = 0; tile < NT; tile++) {
        int base = blockIdx.x * (T1 * NT) + tile * T1;

        for (int i = t; i < T1 * 128; i += 512) {
            int n = i >> 7, k = i & 127;
            sa[n][k] = g_agg1f[(base + n) * 128 + k];
            sh[n][k] = g_h0[(base + n) * 128 + k];
        }
        __syncthreads();

        // Phase A: quarter-row dots
        for (int n = 0; n < T1; n++) {
            const ulonglong2* a2 = (const ulonglong2*)(sa[n] + hq * 32);
            const ulonglong2* h4 = (const ulonglong2*)(sh[n] + hq * 32);
            ull c0 = 0, c1 = 0, c2 = 0, c3 = 0;
            #pragma unroll
            for (int k = 0; k < 8; k++) {
                ulonglong2 pa = a2[k];
                ulonglong2 ph = h4[k];
                c0 = fma2(wl2[2*k],   pa.x, c0);
                c1 = fma2(wl2[2*k+1], pa.y, c1);
                c2 = fma2(wr2[2*k],   ph.x, c2);
                c3 = fma2(wr2[2*k+1], ph.y, c3);
            }
            part[n][t] = blj + ((red2(c0) + red2(c1)) + (red2(c2) + red2(c3)));
        }
        __syncthreads();

        // Phase B: warp w -> node w
        {
            int n = w;
            float v0 = part[n][lane]      + part[n][lane + 128] + part[n][lane + 256] + part[n][lane + 384];
            float v1 = part[n][lane + 32] + part[n][lane + 160] + part[n][lane + 288] + part[n][lane + 416];
            float v2 = part[n][lane + 64] + part[n][lane + 192] + part[n][lane + 320] + part[n][lane + 448];
            float v3 = part[n][lane + 96] + part[n][lane + 224] + part[n][lane + 352] + part[n][lane + 480];
            float s1 = (v0 + v1) + (v2 + v3);
            float s2 = (v0*v0 + v1*v1) + (v2*v2 + v3*v3);
            #pragma unroll
            for (int o = 16; o > 0; o >>= 1) {
                s1 += __shfl_xor_sync(0xFFFFFFFFu, s1, o);
                s2 += __shfl_xor_sync(0xFFFFFFFFu, s2, o);
            }
            float mu = s1 * (1.f / 128.f);
            float var = s2 * (1.f / 128.f) - mu * mu;
            float rstd = rsqrtf(var + LN_EPS);
            sOut[n][lane]      = fmaxf((v0 - mu) * rstd * gv[0] + bv[0], 0.f);
            sOut[n][lane + 32] = fmaxf((v1 - mu) * rstd * gv[1] + bv[1], 0.f);
            sOut[n][lane + 64] = fmaxf((v2 - mu) * rstd * gv[2] + bv[2], 0.f);
            sOut[n][lane + 96] = fmaxf((v3 - mu) * rstd * gv[3] + bv[3], 0.f);
        }
        __syncthreads();

        // Phase C1: head segment dots (16 floats = 4 ulonglong2)
        for (int n = 0; n < T1; n++) {
            const ulonglong2* s2p = (const ulonglong2*)(sOut[n] + q * 16);
            ull c0 = 0, c1 = 0;
            #pragma unroll
            for (int k = 0; k < 4; k++) {
                ulonglong2 pv = s2p[k];
                c0 = fma2(w1p[2*k],   pv.x, c0);
                c1 = fma2(w1p[2*k+1], pv.y, c1);
            }
            part[n][t] = red2(c0) + red2(c1);
        }
        __syncthreads();

        // Phase C2: warp w -> node w
        {
            int n = w;
            float h0 = b1v0, h1 = b1v1;
            #pragma unroll
            for (int qq = 0; qq < 8; qq++) {
                h0 += part[n][qq * 64 + lane];
                h1 += part[n][qq * 64 + 32 + lane];
            }
            float z = fmaxf(h0, 0.f) * w2v0 + fmaxf(h1, 0.f) * w2v1;
            #pragma unroll
            for (int o = 16; o > 0; o >>= 1)
                z += __shfl_xor_sync(0xFFFFFFFFu, z, o);
            if (lane == 0)
                out[base + n] = 1.f / (1.f + expf(-(z + b2s)));
        }
        __syncthreads();   // part/sOut reuse safety across tiles
    }
}

// ---------------- launch ----------------
extern "C" void kernel_launch(void* const* d_in, const int* in_sizes, int n_in,
                              void* d_out, int out_size) {
    const float* x   = (const float*)d_in[0];
    const void*  ei  = d_in[1];
    const float* Wl0 = (const float*)d_in[2];
    const float* bl0 = (const float*)d_in[3];
    const float* Wr0 = (const float*)d_in[4];
    const float* g0  = (const float*)d_in[5];
    const float* be0 = (const float*)d_in[6];
    const float* Wl1 = (const float*)d_in[7];
    const float* bl1 = (const float*)d_in[8];
    const float* Wr1 = (const float*)d_in[9];
    const float* g1  = (const float*)d_in[10];
    const float* be1 = (const float*)d_in[11];
    const float* W1  = (const float*)d_in[12];
    const float* b1  = (const float*)d_in[13];
    const float* W2  = (const float*)d_in[14];
    const float* b2  = (const float*)d_in[15];
    float* out = (float*)d_out;

    int dev = 0, smCount = 0, occ = 0;
    cudaGetDevice(&dev);
    cudaDeviceGetAttribute(&smCount, cudaDevAttrMultiProcessorCount, dev);
    cudaOccupancyMaxActiveBlocksPerMultiprocessor(&occ, k_build, BGT, 0);
    if (occ < 1) occ = 1;
    int G = smCount * occ;
    if (G > 2048) G = 2048;
    if (G < 1) G = 1;

    k_build<<<G, BGT>>>((const int*)ei);                                           // 1
    k_agg0<<<(NN * 32 + 255) / 256, 256>>>(x);                                     // 2
    k_sage0<<<NN / (T0 * NT), 256>>>(x, Wl0, bl0, Wr0, g0, be0);                   // 3
    k_agg1<<<(NN * 32 + 255) / 256, 256>>>();                                      // 4  <- profiled slot
    k_sage1<<<NN / (T1 * NT), 512>>>(Wl1, bl1, Wr1, g1, be1, W1, b1, W2, b2, out); // 5
}